// round 4
// baseline (speedup 1.0000x reference)
#include <cuda_runtime.h>

#define NN    100000   // nodes
#define RR    32       // relations
#define EE    3200000  // edges
#define EMBD  128      // embedding dim
#define HH    32       // hidden dim
#define BBASES 16      // num bases
#define CC    16       // output classes

#define SCAN_BLOCKS ((NN + 1023) / 1024)   // 98

// -------- scratch (static device globals) --------
__device__ float g_deg[RR * NN];                 // 12.8 MB  edge-count per (rel, fr)
__device__ float g_h1[NN * HH];                  // 12.8 MB  hidden1 accumulator
__device__ float g_yb[NN * (BBASES * HH)];       // 204.8 MB yb[n][b*32+h] = emb @ bases1
__device__ float g_w2t[RR * CC * HH];            // 64 KB    w2 transposed to [r][c][h]
__device__ int   g_cnt[NN];                      // histogram of `to`
__device__ int   g_off[NN + 1];                  // group offsets (exclusive scan)
__device__ int   g_pos[NN];                      // running scatter positions
__device__ int   g_bsum[SCAN_BLOCKS];            // per-block scan totals
__device__ int2  g_ev[EE];                       // sorted edges: {(r<<17)|f, bits(val)}

// -------- init --------
__global__ void k_init(const float* __restrict__ bias2, float* __restrict__ out) {
    int i = blockIdx.x * blockDim.x + threadIdx.x;
    int stride = gridDim.x * blockDim.x;
    for (int idx = i; idx < RR * NN; idx += stride) g_deg[idx] = 0.f;
    for (int idx = i; idx < NN * HH; idx += stride) g_h1[idx] = 0.f;
    for (int idx = i; idx < NN; idx += stride) g_cnt[idx] = 0;
    for (int idx = i; idx < NN * CC; idx += stride) out[idx] = bias2[idx & (CC - 1)];
}

// -------- w2t[r][c][h] = sum_b comps2[r,b] * bases2[b,h,c] --------
__global__ void k_w2t(const float* __restrict__ comps2, const float* __restrict__ bases2) {
    int idx = blockIdx.x * blockDim.x + threadIdx.x;
    if (idx >= RR * CC * HH) return;
    int r = idx >> 9;
    int c = (idx >> 5) & (CC - 1);
    int h = idx & (HH - 1);
    float acc = 0.f;
    #pragma unroll
    for (int b = 0; b < BBASES; b++)
        acc += comps2[r * BBASES + b] * bases2[(b * HH + h) * CC + c];
    g_w2t[idx] = acc;
}

// -------- deg + to-histogram --------
__global__ void k_deg(const int* __restrict__ rel, const int* __restrict__ fr,
                      const int* __restrict__ to) {
    int i = blockIdx.x * blockDim.x + threadIdx.x;
    int stride = gridDim.x * blockDim.x;
    for (int e = i; e < EE; e += stride) {
        atomicAdd(&g_deg[rel[e] * NN + fr[e]], 1.0f);
        atomicAdd(&g_cnt[to[e]], 1);
    }
}

// -------- multi-block exclusive scan --------
__global__ void k_scan1() {
    __shared__ int s[1024];
    int tid = threadIdx.x;
    int i = blockIdx.x * 1024 + tid;
    int v = (i < NN) ? g_cnt[i] : 0;
    s[tid] = v;
    __syncthreads();
    #pragma unroll
    for (int d = 1; d < 1024; d <<= 1) {
        int t = (tid >= d) ? s[tid - d] : 0;
        __syncthreads();
        s[tid] += t;
        __syncthreads();
    }
    if (i < NN) g_off[i] = s[tid] - v;
    if (tid == 1023) g_bsum[blockIdx.x] = s[1023];
}

__global__ void k_scan2() {
    __shared__ int s[128];
    int tid = threadIdx.x;
    int v = (tid < SCAN_BLOCKS) ? g_bsum[tid] : 0;
    s[tid] = v;
    __syncthreads();
    #pragma unroll
    for (int d = 1; d < 128; d <<= 1) {
        int t = (tid >= d) ? s[tid - d] : 0;
        __syncthreads();
        s[tid] += t;
        __syncthreads();
    }
    if (tid < SCAN_BLOCKS) g_bsum[tid] = s[tid] - v;
}

__global__ void k_scan3() {
    int i = blockIdx.x * 1024 + threadIdx.x;
    if (i < NN) {
        int o = g_off[i] + g_bsum[i >> 10];
        g_off[i] = o;
        g_pos[i] = o;
    }
    if (i == 0) g_off[NN] = EE;
}

// -------- scatter: to-sorted edge records with precomputed val --------
__global__ void k_scatter(const int* __restrict__ rel, const int* __restrict__ fr,
                          const int* __restrict__ to) {
    int i = blockIdx.x * blockDim.x + threadIdx.x;
    int stride = gridDim.x * blockDim.x;
    for (int e = i; e < EE; e += stride) {
        int r = rel[e], f = fr[e];
        int pos = atomicAdd(&g_pos[to[e]], 1);
        float val = 1.0f / g_deg[r * NN + f];
        g_ev[pos] = make_int2((r << 17) | f, __float_as_int(val));
    }
}

// -------- packed f32x2 FMA (FFMA2 in SASS; only reachable via PTX) --------
__device__ __forceinline__ unsigned long long fma2(unsigned long long a,
                                                   unsigned long long b,
                                                   unsigned long long c) {
    unsigned long long d;
    asm("fma.rn.f32x2 %0, %1, %2, %3;" : "=l"(d) : "l"(a), "l"(b), "l"(c));
    return d;
}

// -------- GEMM: yb = emb @ W  (W[k][b*32+h] = bases1[b][k][h]), packed f32x2 ----
#define GBM 64
#define GBN 128
#define GBK 16
__global__ void k_gemm1(const float* __restrict__ A, const float* __restrict__ bases1) {
    __shared__ float Asd[GBK][2 * GBM];   // A tile, each value duplicated: [k][2m],[k][2m+1]
    __shared__ float Bs[GBK][GBN];
    int tid = threadIdx.x;
    int tx = tid & 31;                    // n-pair lane
    int ty = tid >> 5;                    // 0..7, m-group
    int m0 = blockIdx.y * GBM;
    int n0 = blockIdx.x * GBN;

    int arow = tid >> 2;                  // 0..63
    int acol = (tid & 3) << 2;            // 0,4,8,12
    int brow = tid >> 4;                  // 0..15
    int bcol = (tid & 15) << 3;           // 0..120
    int j  = n0 + bcol;
    int bb = j >> 5;
    int hh = j & 31;
    const float* bsrc = bases1 + bb * (EMBD * HH) + hh;

    unsigned long long acc[8][2];
    #pragma unroll
    for (int i = 0; i < 8; i++) { acc[i][0] = 0ull; acc[i][1] = 0ull; }

    int m_a = m0 + arow;
    for (int k0 = 0; k0 < EMBD; k0 += GBK) {
        float4 av = make_float4(0.f, 0.f, 0.f, 0.f);
        if (m_a < NN) av = *(const float4*)(A + m_a * EMBD + k0 + acol);
        *(float2*)&Asd[acol + 0][2 * arow] = make_float2(av.x, av.x);
        *(float2*)&Asd[acol + 1][2 * arow] = make_float2(av.y, av.y);
        *(float2*)&Asd[acol + 2][2 * arow] = make_float2(av.z, av.z);
        *(float2*)&Asd[acol + 3][2 * arow] = make_float2(av.w, av.w);
        float4 b0 = *(const float4*)(bsrc + (k0 + brow) * HH);
        float4 b1 = *(const float4*)(bsrc + (k0 + brow) * HH + 4);
        *(float4*)&Bs[brow][bcol]     = b0;
        *(float4*)&Bs[brow][bcol + 4] = b1;
        __syncthreads();
        #pragma unroll
        for (int kk = 0; kk < GBK; kk++) {
            unsigned long long bp0 = *(const unsigned long long*)&Bs[kk][2 * tx];
            unsigned long long bp1 = *(const unsigned long long*)&Bs[kk][64 + 2 * tx];
            #pragma unroll
            for (int i = 0; i < 8; i++) {
                unsigned long long ap = *(const unsigned long long*)&Asd[kk][2 * (ty * 8 + i)];
                acc[i][0] = fma2(ap, bp0, acc[i][0]);
                acc[i][1] = fma2(ap, bp1, acc[i][1]);
            }
        }
        __syncthreads();
    }
    #pragma unroll
    for (int i = 0; i < 8; i++) {
        int m = m0 + ty * 8 + i;
        if (m < NN) {
            *(unsigned long long*)&g_yb[m * 512 + n0 + 2 * tx]      = acc[i][0];
            *(unsigned long long*)&g_yb[m * 512 + n0 + 64 + 2 * tx] = acc[i][1];
        }
    }
}

__device__ __forceinline__ void red_add_v4(float* addr, float a, float b, float c, float d) {
    asm volatile("red.global.add.v4.f32 [%0], {%1, %2, %3, %4};"
                 :: "l"(addr), "f"(a), "f"(b), "f"(c), "f"(d) : "memory");
}

// -------- pass1 (sorted by to): block per node n; 4 edges/warp, lane = 4 h's --------
__global__ void k_pass1s(const float* __restrict__ comps1) {
    __shared__ float syb[BBASES * HH];   // 512: yb row of node n
    __shared__ float sc1[RR * BBASES];   // 512: comps1
    int n = blockIdx.x;
    int tid = threadIdx.x;               // 128 threads
    *(float4*)&syb[tid << 2] = *(const float4*)&g_yb[n * 512 + (tid << 2)];
    *(float4*)&sc1[tid << 2] = *(const float4*)&comps1[tid << 2];
    __syncthreads();
    int start = g_off[n], end = g_off[n + 1];
    int lane = tid & 31;
    int w = tid >> 5;
    int sub = lane >> 3;                 // 0..3: which edge in the quad
    int h4 = (lane & 7) << 2;            // h base: 0,4,...,28
    for (int base = start + (w << 2); base < end; base += 16) {
        int e = base + sub;
        if (e < end) {
            int2 ev = g_ev[e];
            int r = ev.x >> 17;
            int f = ev.x & 0x1FFFF;
            float val = __int_as_float(ev.y);
            float a0 = 0.f, a1 = 0.f, a2 = 0.f, a3 = 0.f;
            #pragma unroll
            for (int b = 0; b < BBASES; b++) {
                float c = sc1[r * BBASES + b];
                float4 y = *(const float4*)&syb[b * HH + h4];
                a0 += c * y.x; a1 += c * y.y; a2 += c * y.z; a3 += c * y.w;
            }
            red_add_v4(&g_h1[f * HH + h4], val * a0, val * a1, val * a2, val * a3);
        }
    }
}

// -------- pass2 (sorted by to): block per node; relu fused; 8 edges/warp, lane = 4 c's
__global__ void k_pass2s(const float* __restrict__ bias1, float* __restrict__ out) {
    __shared__ float sh1[HH];
    int n = blockIdx.x;
    int tid = threadIdx.x;               // 128 threads
    if (tid < HH) sh1[tid] = fmaxf(g_h1[n * HH + tid] + bias1[tid], 0.f);
    __syncthreads();
    float4 hv[8];
    #pragma unroll
    for (int q = 0; q < 8; q++) hv[q] = *(const float4*)&sh1[q << 2];

    int start = g_off[n], end = g_off[n + 1];
    int lane = tid & 31;
    int w = tid >> 5;
    int sub = lane >> 2;                 // 0..7: which edge in the octet
    int c0 = (lane & 3) << 2;            // c base: 0,4,8,12
    for (int base = start + (w << 3); base < end; base += 32) {
        int e = base + sub;
        if (e < end) {
            int2 ev = g_ev[e];
            int r = ev.x >> 17;
            int f = ev.x & 0x1FFFF;
            float val = __int_as_float(ev.y);
            const float4* w2 = (const float4*)&g_w2t[(r * CC + c0) * HH];
            float acc[4];
            #pragma unroll
            for (int c = 0; c < 4; c++) {
                float s = 0.f;
                #pragma unroll
                for (int q = 0; q < 8; q++) {
                    float4 b = w2[c * 8 + q];
                    float4 a = hv[q];
                    s += a.x * b.x + a.y * b.y + a.z * b.z + a.w * b.w;
                }
                acc[c] = s * val;
            }
            red_add_v4(&out[f * CC + c0], acc[0], acc[1], acc[2], acc[3]);
        }
    }
}

extern "C" void kernel_launch(void* const* d_in, const int* in_sizes, int n_in,
                              void* d_out, int out_size) {
    const float* emb    = (const float*)d_in[0];
    const float* comps1 = (const float*)d_in[1];
    const float* bases1 = (const float*)d_in[2];
    const float* comps2 = (const float*)d_in[3];
    const float* bases2 = (const float*)d_in[4];
    const float* bias1  = (const float*)d_in[5];
    const float* bias2  = (const float*)d_in[6];
    const int*   rel    = (const int*)d_in[7];
    const int*   fr     = (const int*)d_in[8];
    const int*   to     = (const int*)d_in[9];
    float* out = (float*)d_out;

    k_init<<<12500, 256>>>(bias2, out);
    k_w2t<<<(RR * CC * HH + 255) / 256, 256>>>(comps2, bases2);
    k_deg<<<4096, 256>>>(rel, fr, to);
    k_scan1<<<SCAN_BLOCKS, 1024>>>();
    k_scan2<<<1, 128>>>();
    k_scan3<<<SCAN_BLOCKS, 1024>>>();
    k_scatter<<<4096, 256>>>(rel, fr, to);
    k_gemm1<<<dim3((BBASES * HH) / GBN, (NN + GBM - 1) / GBM), 256>>>(emb, bases1);
    k_pass1s<<<NN, 128>>>(comps1);
    k_pass2s<<<NN, 128>>>(bias1, out);
}